// round 2
// baseline (speedup 1.0000x reference)
#include <cuda_runtime.h>
#include <cstdint>

// Problem constants
static const int E    = 8;
static const int HID  = 2048;
static const int ITR  = 1408;
static const int MPE  = 1024;

// Tiling
static const int BM       = 128;
static const int BK       = 32;
static const int NTHREADS = 256;
static const int SST      = 36;   // smem row stride in words (BK + 4 pad -> conflict-free frags)

// Intermediate scratch: silu(gate)*up, [E*MPE, ITR] fp32 (static device array: allowed)
__device__ float g_down[(size_t)E * MPE * ITR];

__device__ __forceinline__ uint32_t f2tf(float x) {
    uint32_t r;
    asm("cvt.rna.tf32.f32 %0, %1;" : "=r"(r) : "f"(x));
    return r;
}

__device__ __forceinline__ void mma8(float* c, const uint32_t* a, const uint32_t* b) {
    asm volatile(
        "mma.sync.aligned.m16n8k8.row.col.f32.tf32.tf32.f32 "
        "{%0,%1,%2,%3}, {%4,%5,%6,%7}, {%8,%9}, {%0,%1,%2,%3};\n"
        : "+f"(c[0]), "+f"(c[1]), "+f"(c[2]), "+f"(c[3])
        : "r"(a[0]), "r"(a[1]), "r"(a[2]), "r"(a[3]), "r"(b[0]), "r"(b[1]));
}

// MODE 0: gate_up GEMM + silu*up fusion  (A = hidden_states, W = gate_up_weight)
//         out tile n covers 64 gate cols; B tile rows 0..63 = gate rows, 64..127 = up rows.
// MODE 1: down GEMM                     (A = g_down scratch, W = gate_down_weight)
template <int MODE>
__global__ void __launch_bounds__(NTHREADS, 1)
moe_gemm(const float* __restrict__ Aall, const float* __restrict__ Wall,
         const float* __restrict__ Sall, float* __restrict__ Out) {
    constexpr int K  = (MODE == 0) ? HID : ITR;     // 2048 / 1408
    constexpr int KT = K / BK;                      // 64 / 44
    constexpr int KB = K / 128;                     // scale k-blocks: 16 / 11
    constexpr int NW = (MODE == 0) ? 2 * ITR : HID; // weight rows per expert

    extern __shared__ uint32_t smem[];
    uint32_t* sA = smem;                    // 2 * BM * SST
    uint32_t* sB = smem + 2 * BM * SST;     // 2 * BM * SST

    const int e    = blockIdx.z;
    const int m0   = blockIdx.y * BM;
    const int tid  = threadIdx.x;
    const int wid  = tid >> 5;
    const int lane = tid & 31;
    const int g    = lane >> 2;     // groupID
    const int tg   = lane & 3;      // threadID_in_group

    const float* Abase = (MODE == 0) ? Aall : (const float*)g_down;
    const float* A = Abase + (size_t)e * MPE * K + (size_t)m0 * K;
    const float* W = Wall + (size_t)e * NW * K;
    const float* S = Sall + (size_t)e * (NW / 128) * KB;

    const int rb = tid >> 3;        // 0..31: base row of this thread's 4 load chunks
    const int c4 = (tid & 7) * 4;   // float offset within k-tile

    // Per-thread weight row + scale row pointers for its 4 B-tile row chunks
    const float* wp[4];
    const float* sp[4];
    #pragma unroll
    for (int i = 0; i < 4; i++) {
        int brow = rb + 32 * i;
        int wr;
        if (MODE == 0) {
            int n0g = blockIdx.x * 64;
            wr = (brow < 64) ? (n0g + brow) : (ITR + n0g + (brow - 64));
        } else {
            wr = blockIdx.x * 128 + brow;
        }
        wp[i] = W + (size_t)wr * K;
        sp[i] = S + (size_t)(wr >> 7) * KB;
    }

    float acc[16][4];
    #pragma unroll
    for (int i = 0; i < 16; i++)
        #pragma unroll
        for (int j = 0; j < 4; j++) acc[i][j] = 0.f;

    float4 av[4], bv[4];
    float  sc[4];

    auto load_tile = [&](int t) {
        const int k0 = t * BK;
        #pragma unroll
        for (int i = 0; i < 4; i++) {
            av[i] = *(const float4*)(A + (size_t)(rb + 32 * i) * K + k0 + c4);
            bv[i] = *(const float4*)(wp[i] + k0 + c4);
            sc[i] = sp[i][k0 >> 7];
        }
    };

    auto store_tile = [&](int p) {
        uint32_t* dA = sA + p * BM * SST;
        uint32_t* dB = sB + p * BM * SST;
        #pragma unroll
        for (int i = 0; i < 4; i++) {
            int r = rb + 32 * i;
            uint4 ua, ub;
            ua.x = f2tf(av[i].x); ua.y = f2tf(av[i].y);
            ua.z = f2tf(av[i].z); ua.w = f2tf(av[i].w);
            ub.x = f2tf(bv[i].x * sc[i]); ub.y = f2tf(bv[i].y * sc[i]);
            ub.z = f2tf(bv[i].z * sc[i]); ub.w = f2tf(bv[i].w * sc[i]);
            *(uint4*)(dA + r * SST + c4) = ua;
            *(uint4*)(dB + r * SST + c4) = ub;
        }
    };

    auto compute = [&](int p) {
        const uint32_t* cA = sA + p * BM * SST;
        const uint32_t* cB = sB + p * BM * SST;
        const int mr = wid * 16;
        #pragma unroll
        for (int ks = 0; ks < 4; ks++) {
            uint32_t a[4];
            const uint32_t* a0 = cA + (mr + g) * SST + ks * 8 + tg;
            const uint32_t* a1 = cA + (mr + g + 8) * SST + ks * 8 + tg;
            a[0] = a0[0]; a[1] = a1[0]; a[2] = a0[4]; a[3] = a1[4];
            #pragma unroll
            for (int nt = 0; nt < 16; nt++) {
                uint32_t b[2];
                const uint32_t* bp = cB + (nt * 8 + g) * SST + ks * 8 + tg;
                b[0] = bp[0]; b[1] = bp[4];
                mma8(acc[nt], a, b);
            }
        }
    };

    // Double-buffered mainloop with register staging
    load_tile(0);
    store_tile(0);
    __syncthreads();
    for (int t = 1; t < KT; t++) {
        load_tile(t);
        compute((t - 1) & 1);
        store_tile(t & 1);
        __syncthreads();
    }
    compute((KT - 1) & 1);

    // Epilogue
    const int mr = wid * 16;
    if (MODE == 0) {
        float* D = g_down + (size_t)(e * MPE + m0) * ITR;
        const int n0g = blockIdx.x * 64;
        #pragma unroll
        for (int nt = 0; nt < 8; nt++) {
            int col = n0g + nt * 8 + 2 * tg;
            #pragma unroll
            for (int h = 0; h < 2; h++) {   // h=0: row g, h=1: row g+8
                int r = mr + g + h * 8;
                float gx = acc[nt][2 * h],     gy = acc[nt][2 * h + 1];
                float ux = acc[nt + 8][2 * h], uy = acc[nt + 8][2 * h + 1];
                float2 o;
                o.x = (gx / (1.f + __expf(-gx))) * ux;
                o.y = (gy / (1.f + __expf(-gy))) * uy;
                *(float2*)(D + (size_t)r * ITR + col) = o;
            }
        }
    } else {
        float* D = Out + (size_t)(e * MPE + m0) * HID;
        const int n0 = blockIdx.x * 128;
        #pragma unroll
        for (int nt = 0; nt < 16; nt++) {
            int col = n0 + nt * 8 + 2 * tg;
            #pragma unroll
            for (int h = 0; h < 2; h++) {
                int r = mr + g + h * 8;
                float2 o;
                o.x = acc[nt][2 * h];
                o.y = acc[nt][2 * h + 1];
                *(float2*)(D + (size_t)r * HID + col) = o;
            }
        }
    }
}

extern "C" void kernel_launch(void* const* d_in, const int* in_sizes, int n_in,
                              void* d_out, int out_size) {
    const float* hs = (const float*)d_in[0];
    // d_in[1] = tokens_per_expert (uniform 1024/expert, matches reference reshape; unused)
    const float* w1 = (const float*)d_in[2];
    const float* s1 = (const float*)d_in[3];
    const float* w2 = (const float*)d_in[4];
    const float* s2 = (const float*)d_in[5];
    float* out = (float*)d_out;

    const int smem_bytes = 2 * 2 * BM * SST * 4;  // 73728
    cudaFuncSetAttribute(moe_gemm<0>, cudaFuncAttributeMaxDynamicSharedMemorySize, smem_bytes);
    cudaFuncSetAttribute(moe_gemm<1>, cudaFuncAttributeMaxDynamicSharedMemorySize, smem_bytes);

    // GEMM1 + silu*up fusion: grid (1408/64, 1024/128, 8)
    moe_gemm<0><<<dim3(ITR / 64, MPE / BM, E), NTHREADS, smem_bytes>>>(hs, w1, s1, nullptr);
    // GEMM2: grid (2048/128, 1024/128, 8)
    moe_gemm<1><<<dim3(HID / 128, MPE / BM, E), NTHREADS, smem_bytes>>>(nullptr, w2, s2, out);
}

// round 4
// speedup vs baseline: 1.2152x; 1.2152x over previous
#include <cuda_runtime.h>
#include <cstdint>

// Problem constants
static const int E   = 8;
static const int HID = 2048;
static const int ITR = 1408;
static const int MPE = 1024;

// GEMM tiling
static const int BM  = 128;   // M rows per CTA
static const int BNR = 256;   // B-tile rows per CTA (MODE0: 128 out cols x {gate,up})
static const int BK  = 32;    // K per stage
static const int NT  = 256;
static const int SST = 36;    // smem row stride (words): conflict-free frag LDS
static const int AST = BM * SST;    // 4608 words / A stage
static const int BST = BNR * SST;   // 9216 words / B stage
static const int SMEM_BYTES = (3 * AST + 3 * BST) * 4;  // 165888

// Packed (pre-scaled, tf32-rounded) operands + intermediate
__device__ float g_w1[(size_t)E * 2 * ITR * HID];  // rows gate/up interleaved
__device__ float g_w2[(size_t)E * HID * ITR];
__device__ float g_a1[(size_t)E * MPE * HID];
__device__ float g_dn[(size_t)E * MPE * ITR];      // silu(gate)*up, rounded

__device__ __forceinline__ uint32_t f2tf(float x) {
    uint32_t r;
    asm("cvt.rna.tf32.f32 %0, %1;" : "=r"(r) : "f"(x));
    return r;
}
__device__ __forceinline__ float rtf(float x) { return __uint_as_float(f2tf(x)); }

__device__ __forceinline__ uint32_t s2u(const void* p) {
    uint32_t a;
    asm("{ .reg .u64 t; cvta.to.shared.u64 t, %1; cvt.u32.u64 %0, t; }" : "=r"(a) : "l"(p));
    return a;
}
__device__ __forceinline__ void cp16(uint32_t dst, const void* src) {
    asm volatile("cp.async.cg.shared.global [%0], [%1], 16;" :: "r"(dst), "l"(src) : "memory");
}
__device__ __forceinline__ void mma8(float* c, const uint32_t* a, const uint32_t* b) {
    asm volatile(
        "mma.sync.aligned.m16n8k8.row.col.f32.tf32.tf32.f32 "
        "{%0,%1,%2,%3}, {%4,%5,%6,%7}, {%8,%9}, {%0,%1,%2,%3};\n"
        : "+f"(c[0]), "+f"(c[1]), "+f"(c[2]), "+f"(c[3])
        : "r"(a[0]), "r"(a[1]), "r"(a[2]), "r"(a[3]), "r"(b[0]), "r"(b[1]));
}

// ---------------- pack: dequant-scale + tf32-round + layout ----------------
__global__ void __launch_bounds__(NT)
pack_all(const float* __restrict__ hs, const float* __restrict__ w1,
         const float* __restrict__ s1, const float* __restrict__ w2,
         const float* __restrict__ s2) {
    const size_t N1 = (size_t)E * 2 * ITR * (HID / 4);   // w1 float4s
    const size_t N2 = (size_t)E * HID * (ITR / 4);       // w2 float4s
    const size_t N3 = (size_t)E * MPE * (HID / 4);       // hs float4s
    const size_t total = N1 + N2 + N3;
    size_t i = (size_t)blockIdx.x * blockDim.x + threadIdx.x;
    const size_t step = (size_t)gridDim.x * blockDim.x;
    for (; i < total; i += step) {
        if (i < N1) {
            const size_t f = i;
            const int kf = (int)(f % (HID / 4));
            const size_t row = f / (HID / 4);
            const int e = (int)(row / (2 * ITR));
            const int j = (int)(row % (2 * ITR));
            const int wr = (j & 1) ? (ITR + (j >> 1)) : (j >> 1);
            const float s = s1[((size_t)e * (2 * ITR / 128) + (wr >> 7)) * (HID / 128) + (kf >> 5)];
            float4 v = ((const float4*)w1)[((size_t)e * 2 * ITR + wr) * (HID / 4) + kf];
            float4 o;
            o.x = rtf(v.x * s); o.y = rtf(v.y * s); o.z = rtf(v.z * s); o.w = rtf(v.w * s);
            ((float4*)g_w1)[f] = o;
        } else if (i < N1 + N2) {
            const size_t f = i - N1;
            const int kf = (int)(f % (ITR / 4));
            const size_t row = f / (ITR / 4);
            const int e = (int)(row / HID);
            const int n = (int)(row % HID);
            const float s = s2[((size_t)e * (HID / 128) + (n >> 7)) * (ITR / 128) + (kf >> 5)];
            float4 v = ((const float4*)w2)[f];
            float4 o;
            o.x = rtf(v.x * s); o.y = rtf(v.y * s); o.z = rtf(v.z * s); o.w = rtf(v.w * s);
            ((float4*)g_w2)[f] = o;
        } else {
            const size_t f = i - N1 - N2;
            float4 v = ((const float4*)hs)[f];
            float4 o;
            o.x = rtf(v.x); o.y = rtf(v.y); o.z = rtf(v.z); o.w = rtf(v.w);
            ((float4*)g_a1)[f] = o;
        }
    }
}

// ---------------- fused GEMM ----------------
// MODE 0: gate_up (K=2048) + silu*up -> g_dn.  B rows interleaved gate/up.
// MODE 1: down    (K=1408) -> Out.
template <int MODE>
__global__ void __launch_bounds__(NT, 1)
moe_gemm(float* __restrict__ Out) {
    constexpr int K  = (MODE == 0) ? HID : ITR;
    constexpr int KT = K / BK;                               // 64 / 44
    constexpr int NWROWS = (MODE == 0) ? 2 * ITR : HID;      // B rows per expert

    extern __shared__ float sm[];
    const uint32_t sb = s2u(sm);
    const int tid = threadIdx.x, wid = tid >> 5, lane = tid & 31;
    const int g = lane >> 2, tg = lane & 3;
    const int e = blockIdx.z, m0 = blockIdx.y * BM, nb = blockIdx.x;

    const float* Ag = ((MODE == 0) ? g_a1 : g_dn) + ((size_t)e * MPE + m0) * K;
    const float* Bg = ((MODE == 0) ? g_w1 : g_w2) + ((size_t)e * NWROWS + (size_t)nb * BNR) * K;

    // per-thread cp.async assignments (chunk = 16B)
    const int ar = (tid * 4) >> 3;        // not used; keep simple per-iter calc
    (void)ar;

    auto issue = [&](int t) {
        const int buf = t % 3;
        const int k0 = t * BK;
        #pragma unroll
        for (int i = 0; i < 4; i++) {                // A: 1024 chunks
            int ci = tid + i * NT;
            int r = ci >> 3, c = ci & 7;
            uint32_t dst = sb + (uint32_t)(buf * AST + r * SST) * 4 + c * 16;
            cp16(dst, Ag + (size_t)r * K + k0 + c * 4);
        }
        #pragma unroll
        for (int i = 0; i < 8; i++) {                // B: 2048 chunks
            int ci = tid + i * NT;
            int r = ci >> 3, c = ci & 7;
            uint32_t dst = sb + (uint32_t)(3 * AST + buf * BST + r * SST) * 4 + c * 16;
            cp16(dst, Bg + (size_t)r * K + k0 + c * 4);
        }
    };

    float acc[4][8][4];
    #pragma unroll
    for (int a = 0; a < 4; a++)
        #pragma unroll
        for (int b = 0; b < 8; b++)
            #pragma unroll
            for (int c = 0; c < 4; c++) acc[a][b][c] = 0.f;

    const int wm = (wid >> 2) * 64;   // warp m-offset (0/64)
    const int wn = (wid & 3) * 64;    // warp n-offset in B rows (0/64/128/192)

    auto compute = [&](int buf) {
        const uint32_t* As = (const uint32_t*)sm + buf * AST;
        const uint32_t* Bs = (const uint32_t*)sm + 3 * AST + buf * BST;
        #pragma unroll
        for (int ks = 0; ks < 4; ks++) {
            uint32_t af[4][4], bf[8][2];
            #pragma unroll
            for (int mi = 0; mi < 4; mi++) {
                const uint32_t* p0 = As + (wm + mi * 16 + g) * SST + ks * 8 + tg;
                const uint32_t* p1 = p0 + 8 * SST;
                af[mi][0] = p0[0]; af[mi][1] = p1[0]; af[mi][2] = p0[4]; af[mi][3] = p1[4];
            }
            #pragma unroll
            for (int ni = 0; ni < 8; ni++) {
                const uint32_t* p = Bs + (wn + ni * 8 + g) * SST + ks * 8 + tg;
                bf[ni][0] = p[0]; bf[ni][1] = p[4];
            }
            #pragma unroll
            for (int mi = 0; mi < 4; mi++)
                #pragma unroll
                for (int ni = 0; ni < 8; ni++)
                    mma8(acc[mi][ni], af[mi], bf[ni]);
        }
    };

    // ---- 3-stage cp.async pipeline, one barrier per k-tile ----
    issue(0);
    asm volatile("cp.async.commit_group;" ::: "memory");
    issue(1);
    asm volatile("cp.async.commit_group;" ::: "memory");
    for (int t = 0; t < KT; t++) {
        asm volatile("cp.async.wait_group 1;" ::: "memory");
        __syncthreads();
        if (t + 2 < KT) issue(t + 2);
        asm volatile("cp.async.commit_group;" ::: "memory");
        compute(t % 3);
    }

    // ---- epilogue ----
    if (MODE == 0) {
        // acc[mi][ni]: c0/c1 = (gate, up) of out-col n, rows g / g+8
        const int ncol = nb * (BNR / 2) + (wn >> 1) + tg;   // + ni*4
        float* D = g_dn + ((size_t)e * MPE + m0 + wm + g) * ITR + ncol;
        #pragma unroll
        for (int mi = 0; mi < 4; mi++) {
            float* Dr0 = D + (size_t)(mi * 16) * ITR;
            float* Dr1 = Dr0 + (size_t)8 * ITR;
            #pragma unroll
            for (int ni = 0; ni < 8; ni++) {
                float g0 = acc[mi][ni][0], u0 = acc[mi][ni][1];
                float g1 = acc[mi][ni][2], u1 = acc[mi][ni][3];
                Dr0[ni * 4] = rtf((g0 / (1.f + __expf(-g0))) * u0);
                Dr1[ni * 4] = rtf((g1 / (1.f + __expf(-g1))) * u1);
            }
        }
    } else {
        const int ncol = nb * BNR + wn + 2 * tg;            // + ni*8
        float* D = Out + ((size_t)e * MPE + m0 + wm + g) * HID + ncol;
        #pragma unroll
        for (int mi = 0; mi < 4; mi++) {
            float* Dr0 = D + (size_t)(mi * 16) * HID;
            float* Dr1 = Dr0 + (size_t)8 * HID;
            #pragma unroll
            for (int ni = 0; ni < 8; ni++) {
                float2 o0 = {acc[mi][ni][0], acc[mi][ni][1]};
                float2 o1 = {acc[mi][ni][2], acc[mi][ni][3]};
                *(float2*)(Dr0 + ni * 8) = o0;
                *(float2*)(Dr1 + ni * 8) = o1;
            }
        }
    }
}

extern "C" void kernel_launch(void* const* d_in, const int* in_sizes, int n_in,
                              void* d_out, int out_size) {
    const float* hs = (const float*)d_in[0];
    // d_in[1] = tokens_per_expert (uniform 1024/expert; matches reference reshape)
    const float* w1 = (const float*)d_in[2];
    const float* s1 = (const float*)d_in[3];
    const float* w2 = (const float*)d_in[4];
    const float* s2 = (const float*)d_in[5];
    float* out = (float*)d_out;

    cudaFuncSetAttribute(moe_gemm<0>, cudaFuncAttributeMaxDynamicSharedMemorySize, SMEM_BYTES);
    cudaFuncSetAttribute(moe_gemm<1>, cudaFuncAttributeMaxDynamicSharedMemorySize, SMEM_BYTES);

    pack_all<<<4096, NT>>>(hs, w1, s1, w2, s2);
    // GEMM1 + silu*up: grid (2816/256, 8, 8) = (11, 8, 8)
    moe_gemm<0><<<dim3(2 * ITR / BNR, MPE / BM, E), NT, SMEM_BYTES>>>(nullptr);
    // GEMM2: grid (2048/256, 8, 8) = (8, 8, 8)
    moe_gemm<1><<<dim3(HID / BNR, MPE / BM, E), NT, SMEM_BYTES>>>(out);
}

// round 5
// speedup vs baseline: 1.2200x; 1.0039x over previous
#include <cuda_runtime.h>
#include <cstdint>

// Problem constants
static const int E   = 8;
static const int HID = 2048;
static const int ITR = 1408;
static const int MPE = 1024;

// GEMM tiling
static const int BM  = 128;   // M rows per CTA
static const int BNR = 256;   // B-tile rows per CTA (MODE0: 128 out cols x {gate,up})
static const int BK  = 64;    // K per stage
static const int NT  = 512;   // 16 warps
static const int SST = 68;    // smem row stride (words): conflict-free frag LDS (4g+tg mod 32)
static const int AST = BM * SST;    // 8704 words / A stage
static const int BST = BNR * SST;   // 17408 words / B stage
static const int SMEM_BYTES = 2 * (AST + BST) * 4;  // 208896

// Packed (pre-scaled, tf32-rounded) operands + intermediate
__device__ float g_w1[(size_t)E * 2 * ITR * HID];  // rows gate/up interleaved
__device__ float g_w2[(size_t)E * HID * ITR];
__device__ float g_a1[(size_t)E * MPE * HID];
__device__ float g_dn[(size_t)E * MPE * ITR];      // silu(gate)*up, rounded

__device__ __forceinline__ uint32_t f2tf(float x) {
    uint32_t r;
    asm("cvt.rna.tf32.f32 %0, %1;" : "=r"(r) : "f"(x));
    return r;
}
__device__ __forceinline__ float rtf(float x) { return __uint_as_float(f2tf(x)); }

__device__ __forceinline__ uint32_t s2u(const void* p) {
    uint32_t a;
    asm("{ .reg .u64 t; cvta.to.shared.u64 t, %1; cvt.u32.u64 %0, t; }" : "=r"(a) : "l"(p));
    return a;
}
__device__ __forceinline__ void cp16(uint32_t dst, const void* src) {
    asm volatile("cp.async.cg.shared.global [%0], [%1], 16;" :: "r"(dst), "l"(src) : "memory");
}
__device__ __forceinline__ void mma8(float* c, const uint32_t* a, const uint32_t* b) {
    asm volatile(
        "mma.sync.aligned.m16n8k8.row.col.f32.tf32.tf32.f32 "
        "{%0,%1,%2,%3}, {%4,%5,%6,%7}, {%8,%9}, {%0,%1,%2,%3};\n"
        : "+f"(c[0]), "+f"(c[1]), "+f"(c[2]), "+f"(c[3])
        : "r"(a[0]), "r"(a[1]), "r"(a[2]), "r"(a[3]), "r"(b[0]), "r"(b[1]));
}

// ---------------- pack: dequant-scale + tf32-round + layout ----------------
__global__ void __launch_bounds__(256)
pack_all(const float* __restrict__ hs, const float* __restrict__ w1,
         const float* __restrict__ s1, const float* __restrict__ w2,
         const float* __restrict__ s2) {
    const size_t N1 = (size_t)E * 2 * ITR * (HID / 4);   // w1 float4s
    const size_t N2 = (size_t)E * HID * (ITR / 4);       // w2 float4s
    const size_t N3 = (size_t)E * MPE * (HID / 4);       // hs float4s
    const size_t total = N1 + N2 + N3;
    size_t i = (size_t)blockIdx.x * blockDim.x + threadIdx.x;
    const size_t step = (size_t)gridDim.x * blockDim.x;
    for (; i < total; i += step) {
        if (i < N1) {
            const size_t f = i;
            const int kf = (int)(f % (HID / 4));
            const size_t row = f / (HID / 4);
            const int e = (int)(row / (2 * ITR));
            const int j = (int)(row % (2 * ITR));
            const int wr = (j & 1) ? (ITR + (j >> 1)) : (j >> 1);
            const float s = s1[((size_t)e * (2 * ITR / 128) + (wr >> 7)) * (HID / 128) + (kf >> 5)];
            float4 v = ((const float4*)w1)[((size_t)e * 2 * ITR + wr) * (HID / 4) + kf];
            float4 o;
            o.x = rtf(v.x * s); o.y = rtf(v.y * s); o.z = rtf(v.z * s); o.w = rtf(v.w * s);
            ((float4*)g_w1)[f] = o;
        } else if (i < N1 + N2) {
            const size_t f = i - N1;
            const int kf = (int)(f % (ITR / 4));
            const size_t row = f / (ITR / 4);
            const int e = (int)(row / HID);
            const int n = (int)(row % HID);
            const float s = s2[((size_t)e * (HID / 128) + (n >> 7)) * (ITR / 128) + (kf >> 5)];
            float4 v = ((const float4*)w2)[f];
            float4 o;
            o.x = rtf(v.x * s); o.y = rtf(v.y * s); o.z = rtf(v.z * s); o.w = rtf(v.w * s);
            ((float4*)g_w2)[f] = o;
        } else {
            const size_t f = i - N1 - N2;
            float4 v = ((const float4*)hs)[f];
            float4 o;
            o.x = rtf(v.x); o.y = rtf(v.y); o.z = rtf(v.z); o.w = rtf(v.w);
            ((float4*)g_a1)[f] = o;
        }
    }
}

// ---------------- fused GEMM ----------------
// MODE 0: gate_up (K=2048) + silu*up -> g_dn.  B rows interleaved gate/up.
// MODE 1: down    (K=1408) -> Out.
template <int MODE>
__global__ void __launch_bounds__(NT, 1)
moe_gemm(float* __restrict__ Out) {
    constexpr int K  = (MODE == 0) ? HID : ITR;
    constexpr int KT = K / BK;                               // 32 / 22
    constexpr int NWROWS = (MODE == 0) ? 2 * ITR : HID;      // B rows per expert

    extern __shared__ float sm[];
    const uint32_t sb = s2u(sm);
    const int tid = threadIdx.x, wid = tid >> 5, lane = tid & 31;
    const int g = lane >> 2, tg = lane & 3;
    const int e = blockIdx.z, m0 = blockIdx.y * BM, nb = blockIdx.x;

    const float* Ag = ((MODE == 0) ? g_a1 : g_dn) + ((size_t)e * MPE + m0) * K;
    const float* Bg = ((MODE == 0) ? g_w1 : g_w2) + ((size_t)e * NWROWS + (size_t)nb * BNR) * K;

    // cp.async: 16B chunks, 16 chunks per 64-float row
    const int cr = tid >> 4;        // row group base (0..31)
    const int cc = tid & 15;        // chunk within row

    auto issue = [&](int t) {
        const int buf = t & 1;
        const int k0 = t * BK;
        const uint32_t abase = sb + (uint32_t)(buf * AST) * 4;
        const uint32_t bbase = sb + (uint32_t)(2 * AST + buf * BST) * 4;
        #pragma unroll
        for (int i = 0; i < 4; i++) {                // A: 128 rows
            int r = cr + 32 * i;
            cp16(abase + (uint32_t)r * SST * 4 + cc * 16, Ag + (size_t)r * K + k0 + cc * 4);
        }
        #pragma unroll
        for (int i = 0; i < 8; i++) {                // B: 256 rows
            int r = cr + 32 * i;
            cp16(bbase + (uint32_t)r * SST * 4 + cc * 16, Bg + (size_t)r * K + k0 + cc * 4);
        }
    };

    float acc[4][4][4];
    #pragma unroll
    for (int a = 0; a < 4; a++)
        #pragma unroll
        for (int b = 0; b < 4; b++)
            #pragma unroll
            for (int c = 0; c < 4; c++) acc[a][b][c] = 0.f;

    const int wm = (wid >> 3) * 64;   // warp m-offset (0/64)
    const int wn = (wid & 7) * 32;    // warp n-offset in B rows (0..224)

    auto compute = [&](int buf) {
        const uint32_t* As = (const uint32_t*)sm + buf * AST;
        const uint32_t* Bs = (const uint32_t*)sm + 2 * AST + buf * BST;
        #pragma unroll
        for (int ks = 0; ks < 8; ks++) {
            uint32_t af[4][4], bf[4][2];
            #pragma unroll
            for (int mi = 0; mi < 4; mi++) {
                const uint32_t* p0 = As + (wm + mi * 16 + g) * SST + ks * 8 + tg;
                const uint32_t* p1 = p0 + 8 * SST;
                af[mi][0] = p0[0]; af[mi][1] = p1[0]; af[mi][2] = p0[4]; af[mi][3] = p1[4];
            }
            #pragma unroll
            for (int ni = 0; ni < 4; ni++) {
                const uint32_t* p = Bs + (wn + ni * 8 + g) * SST + ks * 8 + tg;
                bf[ni][0] = p[0]; bf[ni][1] = p[4];
            }
            #pragma unroll
            for (int mi = 0; mi < 4; mi++)
                #pragma unroll
                for (int ni = 0; ni < 4; ni++)
                    mma8(acc[mi][ni], af[mi], bf[ni]);
        }
    };

    // ---- 2-stage pipeline: prefetch distance = one full 64-K tile ----
    issue(0);
    asm volatile("cp.async.commit_group;" ::: "memory");
    for (int t = 0; t < KT; t++) {
        asm volatile("cp.async.wait_group 0;" ::: "memory");
        __syncthreads();
        if (t + 1 < KT) {
            issue(t + 1);
            asm volatile("cp.async.commit_group;" ::: "memory");
        }
        compute(t & 1);
    }

    // ---- epilogue ----
    if (MODE == 0) {
        // acc[mi][ni]: c0/c1 = (gate, up) of out-col, rows g / g+8
        const int ncol = nb * (BNR / 2) + (wn >> 1) + tg;   // + ni*4
        float* D = g_dn + ((size_t)e * MPE + m0 + wm + g) * ITR + ncol;
        #pragma unroll
        for (int mi = 0; mi < 4; mi++) {
            float* Dr0 = D + (size_t)(mi * 16) * ITR;
            float* Dr1 = Dr0 + (size_t)8 * ITR;
            #pragma unroll
            for (int ni = 0; ni < 4; ni++) {
                float g0 = acc[mi][ni][0], u0 = acc[mi][ni][1];
                float g1 = acc[mi][ni][2], u1 = acc[mi][ni][3];
                Dr0[ni * 4] = rtf((g0 / (1.f + __expf(-g0))) * u0);
                Dr1[ni * 4] = rtf((g1 / (1.f + __expf(-g1))) * u1);
            }
        }
    } else {
        const int ncol = nb * BNR + wn + 2 * tg;            // + ni*8
        float* D = Out + ((size_t)e * MPE + m0 + wm + g) * HID + ncol;
        #pragma unroll
        for (int mi = 0; mi < 4; mi++) {
            float* Dr0 = D + (size_t)(mi * 16) * HID;
            float* Dr1 = Dr0 + (size_t)8 * HID;
            #pragma unroll
            for (int ni = 0; ni < 4; ni++) {
                float2 o0 = {acc[mi][ni][0], acc[mi][ni][1]};
                float2 o1 = {acc[mi][ni][2], acc[mi][ni][3]};
                *(float2*)(Dr0 + ni * 8) = o0;
                *(float2*)(Dr1 + ni * 8) = o1;
            }
        }
    }
}

extern "C" void kernel_launch(void* const* d_in, const int* in_sizes, int n_in,
                              void* d_out, int out_size) {
    const float* hs = (const float*)d_in[0];
    // d_in[1] = tokens_per_expert (uniform 1024/expert; matches reference reshape)
    const float* w1 = (const float*)d_in[2];
    const float* s1 = (const float*)d_in[3];
    const float* w2 = (const float*)d_in[4];
    const float* s2 = (const float*)d_in[5];
    float* out = (float*)d_out;

    cudaFuncSetAttribute(moe_gemm<0>, cudaFuncAttributeMaxDynamicSharedMemorySize, SMEM_BYTES);
    cudaFuncSetAttribute(moe_gemm<1>, cudaFuncAttributeMaxDynamicSharedMemorySize, SMEM_BYTES);

    pack_all<<<4096, 256>>>(hs, w1, s1, w2, s2);
    // GEMM1 + silu*up: grid (2816/256, 8, 8) = (11, 8, 8)
    moe_gemm<0><<<dim3(2 * ITR / BNR, MPE / BM, E), NT, SMEM_BYTES>>>(nullptr);
    // GEMM2: grid (2048/256, 8, 8) = (8, 8, 8)
    moe_gemm<1><<<dim3(HID / BNR, MPE / BM, E), NT, SMEM_BYTES>>>(out);
}

// round 6
// speedup vs baseline: 2.0752x; 1.7010x over previous
#include <cuda_runtime.h>
#include <cuda_fp16.h>
#include <cstdint>

// Problem constants
static const int E   = 8;
static const int HID = 2048;
static const int ITR = 1408;
static const int MPE = 1024;

// GEMM tiling (fp16 operands)
static const int BM  = 128;   // M rows per CTA
static const int BNR = 256;   // B-tile rows per CTA (MODE0: 128 out cols x {gate,up})
static const int BK  = 64;    // K halves per stage (= 128B row)
static const int NT  = 512;   // 16 warps
static const int SST = 36;    // smem row stride in 4B words (32 data + 4 pad) -> conflict-free frags
static const int AST = BM * SST;    // 4608 words / A stage
static const int BST = BNR * SST;   // 9216 words / B stage
static const int SMEM_BYTES = 2 * (AST + BST) * 4;  // 110592

// Packed (pre-scaled, fp16-rounded) operands + intermediate
__device__ __half g_w1[(size_t)E * 2 * ITR * HID];  // rows gate/up interleaved
__device__ __half g_w2[(size_t)E * HID * ITR];
__device__ __half g_a1[(size_t)E * MPE * HID];
__device__ __half g_dn[(size_t)E * MPE * ITR];      // silu(gate)*up, fp16

__device__ __forceinline__ uint32_t s2u(const void* p) {
    uint32_t a;
    asm("{ .reg .u64 t; cvta.to.shared.u64 t, %1; cvt.u32.u64 %0, t; }" : "=r"(a) : "l"(p));
    return a;
}
__device__ __forceinline__ void cp16(uint32_t dst, const void* src) {
    asm volatile("cp.async.cg.shared.global [%0], [%1], 16;" :: "r"(dst), "l"(src) : "memory");
}
__device__ __forceinline__ void mma16(float* c, const uint32_t* a, const uint32_t* b) {
    asm volatile(
        "mma.sync.aligned.m16n8k16.row.col.f32.f16.f16.f32 "
        "{%0,%1,%2,%3}, {%4,%5,%6,%7}, {%8,%9}, {%0,%1,%2,%3};\n"
        : "+f"(c[0]), "+f"(c[1]), "+f"(c[2]), "+f"(c[3])
        : "r"(a[0]), "r"(a[1]), "r"(a[2]), "r"(a[3]), "r"(b[0]), "r"(b[1]));
}

// ---------------- pack: dequant-scale + fp16-round + layout ----------------
__global__ void __launch_bounds__(256)
pack_all(const float* __restrict__ hs, const float* __restrict__ w1,
         const float* __restrict__ s1, const float* __restrict__ w2,
         const float* __restrict__ s2) {
    const size_t N1 = (size_t)E * 2 * ITR * (HID / 4);   // w1 float4 groups
    const size_t N2 = (size_t)E * HID * (ITR / 4);       // w2
    const size_t N3 = (size_t)E * MPE * (HID / 4);       // hs
    const size_t total = N1 + N2 + N3;
    size_t i = (size_t)blockIdx.x * blockDim.x + threadIdx.x;
    const size_t step = (size_t)gridDim.x * blockDim.x;
    for (; i < total; i += step) {
        if (i < N1) {
            const size_t f = i;
            const int kf = (int)(f % (HID / 4));
            const size_t row = f / (HID / 4);
            const int e = (int)(row / (2 * ITR));
            const int j = (int)(row % (2 * ITR));
            const int wr = (j & 1) ? (ITR + (j >> 1)) : (j >> 1);
            const float s = s1[((size_t)e * (2 * ITR / 128) + (wr >> 7)) * (HID / 128) + (kf >> 5)];
            float4 v = ((const float4*)w1)[((size_t)e * 2 * ITR + wr) * (HID / 4) + kf];
            ((__half2*)g_w1)[2 * f]     = __floats2half2_rn(v.x * s, v.y * s);
            ((__half2*)g_w1)[2 * f + 1] = __floats2half2_rn(v.z * s, v.w * s);
        } else if (i < N1 + N2) {
            const size_t f = i - N1;
            const int kf = (int)(f % (ITR / 4));
            const size_t row = f / (ITR / 4);
            const int e = (int)(row / HID);
            const int n = (int)(row % HID);
            const float s = s2[((size_t)e * (HID / 128) + (n >> 7)) * (ITR / 128) + (kf >> 5)];
            float4 v = ((const float4*)w2)[f];
            ((__half2*)g_w2)[2 * f]     = __floats2half2_rn(v.x * s, v.y * s);
            ((__half2*)g_w2)[2 * f + 1] = __floats2half2_rn(v.z * s, v.w * s);
        } else {
            const size_t f = i - N1 - N2;
            float4 v = ((const float4*)hs)[f];
            ((__half2*)g_a1)[2 * f]     = __floats2half2_rn(v.x, v.y);
            ((__half2*)g_a1)[2 * f + 1] = __floats2half2_rn(v.z, v.w);
        }
    }
}

// ---------------- fused GEMM (fp16 mma, fp32 accumulate) ----------------
// MODE 0: gate_up (K=2048) + silu*up -> g_dn.  B rows interleaved gate/up.
// MODE 1: down    (K=1408) -> Out (fp32).
template <int MODE>
__global__ void __launch_bounds__(NT, 1)
moe_gemm(float* __restrict__ Out) {
    constexpr int K  = (MODE == 0) ? HID : ITR;          // in halves
    constexpr int KT = K / BK;                           // 32 / 22
    constexpr int NWROWS = (MODE == 0) ? 2 * ITR : HID;

    extern __shared__ float sm[];
    const uint32_t sb = s2u(sm);
    const int tid = threadIdx.x, wid = tid >> 5, lane = tid & 31;
    const int g = lane >> 2, tg = lane & 3;
    const int e = blockIdx.z, m0 = blockIdx.y * BM, nb = blockIdx.x;

    const __half* Ag = ((MODE == 0) ? g_a1 : g_dn) + ((size_t)e * MPE + m0) * K;
    const __half* Bg = ((MODE == 0) ? g_w1 : g_w2) + ((size_t)e * NWROWS + (size_t)nb * BNR) * K;

    // cp.async: 16B chunks (8 halves); 8 chunks per 64-half row
    auto issue = [&](int t) {
        const int buf = t & 1;
        const int k0 = t * BK;
        const uint32_t abase = sb + (uint32_t)(buf * AST) * 4;
        const uint32_t bbase = sb + (uint32_t)(2 * AST + buf * BST) * 4;
        #pragma unroll
        for (int i = 0; i < 2; i++) {                // A: 1024 chunks
            int ci = tid + i * NT;
            int r = ci >> 3, c = ci & 7;
            cp16(abase + (uint32_t)r * (SST * 4) + c * 16, Ag + (size_t)r * K + k0 + c * 8);
        }
        #pragma unroll
        for (int i = 0; i < 4; i++) {                // B: 2048 chunks
            int ci = tid + i * NT;
            int r = ci >> 3, c = ci & 7;
            cp16(bbase + (uint32_t)r * (SST * 4) + c * 16, Bg + (size_t)r * K + k0 + c * 8);
        }
    };

    float acc[4][4][4];
    #pragma unroll
    for (int a = 0; a < 4; a++)
        #pragma unroll
        for (int b = 0; b < 4; b++)
            #pragma unroll
            for (int c = 0; c < 4; c++) acc[a][b][c] = 0.f;

    const int wm = (wid >> 3) * 64;   // warp m-offset (0/64)
    const int wn = (wid & 7) * 32;    // warp n-offset in B rows (0..224)

    auto compute = [&](int buf) {
        const uint32_t* As = (const uint32_t*)sm + buf * AST;
        const uint32_t* Bs = (const uint32_t*)sm + 2 * AST + buf * BST;
        #pragma unroll
        for (int ks = 0; ks < 4; ks++) {             // k16 steps (8 words each)
            uint32_t af[4][4], bf[4][2];
            #pragma unroll
            for (int mi = 0; mi < 4; mi++) {
                const uint32_t* p0 = As + (wm + mi * 16 + g) * SST + ks * 8 + tg;
                const uint32_t* p1 = p0 + 8 * SST;
                af[mi][0] = p0[0]; af[mi][1] = p1[0]; af[mi][2] = p0[4]; af[mi][3] = p1[4];
            }
            #pragma unroll
            for (int ni = 0; ni < 4; ni++) {
                const uint32_t* p = Bs + (wn + ni * 8 + g) * SST + ks * 8 + tg;
                bf[ni][0] = p[0]; bf[ni][1] = p[4];
            }
            #pragma unroll
            for (int mi = 0; mi < 4; mi++)
                #pragma unroll
                for (int ni = 0; ni < 4; ni++)
                    mma16(acc[mi][ni], af[mi], bf[ni]);
        }
    };

    // ---- 2-stage pipeline ----
    issue(0);
    asm volatile("cp.async.commit_group;" ::: "memory");
    for (int t = 0; t < KT; t++) {
        asm volatile("cp.async.wait_group 0;" ::: "memory");
        __syncthreads();
        if (t + 1 < KT) {
            issue(t + 1);
            asm volatile("cp.async.commit_group;" ::: "memory");
        }
        compute(t & 1);
    }

    // ---- epilogue ----
    if (MODE == 0) {
        // c0/c1 = (gate, up) of one out-col (B cols 2tg, 2tg+1), rows g / g+8 via c2/c3
        const int ncol = nb * (BNR / 2) + (wn >> 1) + tg;   // + ni*4
        __half* D = g_dn + ((size_t)e * MPE + m0 + wm + g) * ITR + ncol;
        #pragma unroll
        for (int mi = 0; mi < 4; mi++) {
            __half* Dr0 = D + (size_t)(mi * 16) * ITR;
            __half* Dr1 = Dr0 + (size_t)8 * ITR;
            #pragma unroll
            for (int ni = 0; ni < 4; ni++) {
                float g0 = acc[mi][ni][0], u0 = acc[mi][ni][1];
                float g1 = acc[mi][ni][2], u1 = acc[mi][ni][3];
                Dr0[ni * 4] = __float2half_rn((g0 / (1.f + __expf(-g0))) * u0);
                Dr1[ni * 4] = __float2half_rn((g1 / (1.f + __expf(-g1))) * u1);
            }
        }
    } else {
        const int ncol = nb * BNR + wn + 2 * tg;            // + ni*8
        float* D = Out + ((size_t)e * MPE + m0 + wm + g) * HID + ncol;
        #pragma unroll
        for (int mi = 0; mi < 4; mi++) {
            float* Dr0 = D + (size_t)(mi * 16) * HID;
            float* Dr1 = Dr0 + (size_t)8 * HID;
            #pragma unroll
            for (int ni = 0; ni < 4; ni++) {
                float2 o0 = {acc[mi][ni][0], acc[mi][ni][1]};
                float2 o1 = {acc[mi][ni][2], acc[mi][ni][3]};
                *(float2*)(Dr0 + ni * 8) = o0;
                *(float2*)(Dr1 + ni * 8) = o1;
            }
        }
    }
}

extern "C" void kernel_launch(void* const* d_in, const int* in_sizes, int n_in,
                              void* d_out, int out_size) {
    const float* hs = (const float*)d_in[0];
    // d_in[1] = tokens_per_expert (uniform 1024/expert; matches reference reshape)
    const float* w1 = (const float*)d_in[2];
    const float* s1 = (const float*)d_in[3];
    const float* w2 = (const float*)d_in[4];
    const float* s2 = (const float*)d_in[5];
    float* out = (float*)d_out;

    cudaFuncSetAttribute(moe_gemm<0>, cudaFuncAttributeMaxDynamicSharedMemorySize, SMEM_BYTES);
    cudaFuncSetAttribute(moe_gemm<1>, cudaFuncAttributeMaxDynamicSharedMemorySize, SMEM_BYTES);

    pack_all<<<4096, 256>>>(hs, w1, s1, w2, s2);
    // GEMM1 + silu*up: grid (2816/256, 8, 8) = (11, 8, 8)
    moe_gemm<0><<<dim3(2 * ITR / BNR, MPE / BM, E), NT, SMEM_BYTES>>>(nullptr);
    // GEMM2: grid (2048/256, 8, 8) = (8, 8, 8)
    moe_gemm<1><<<dim3(HID / BNR, MPE / BM, E), NT, SMEM_BYTES>>>(out);
}